// round 8
// baseline (speedup 1.0000x reference)
#include <cuda_runtime.h>
#include <cstdint>

// Problem constants
#define ROWS_TOTAL 16384      // 4 * 4096 (batch * seq)
#define DIMK 4096             // inner dim
#define RR 8                  // LoRA rank
#define NL 3                  // number of LoRAs
#define LRTOT 24              // NL * RR
#define OUT_DIM 12288         // NL * 4096
#define LORA_OUT 4096

#define NXA (ROWS_TOTAL * LRTOT)   // 393216
#define KS  4                      // split-K slices
#define DKC 16                     // d per chunk
#define BROWS 256                  // rows per xa block

typedef unsigned long long ull;

// -------- scratch (no allocations allowed) --------
__device__ float2 g_Apk2[(DIMK / 2) * LRTOT];  // A packed as d-pairs: [d2][lr]
__device__ float  g_xap[KS * NXA];             // XA partials per k-slice

__device__ __forceinline__ void ffma2(ull& acc, ull a, ull b) {
    asm("fma.rn.f32x2 %0, %1, %2, %0;" : "+l"(acc) : "l"(a), "l"(b));
}

__device__ __forceinline__ void cp_async16(void* smem_dst, const void* gptr) {
    unsigned s = (unsigned)__cvta_generic_to_shared(smem_dst);
    asm volatile("cp.async.cg.shared.global [%0], [%1], 16;\n" :: "r"(s), "l"(gptr));
}
__device__ __forceinline__ void cp_commit() {
    asm volatile("cp.async.commit_group;\n" ::: "memory");
}
__device__ __forceinline__ void cp_wait1() {
    asm volatile("cp.async.wait_group 1;\n" ::: "memory");
}
__device__ __forceinline__ void cp_wait0() {
    asm volatile("cp.async.wait_group 0;\n" ::: "memory");
}

// ============================================================
// k0: pack A0/A1/A2 ([dim][r] row-major) -> g_Apk2 [d2][lr] float2
// ============================================================
__global__ void pack_A_kernel(const float* __restrict__ A0,
                              const float* __restrict__ A1,
                              const float* __restrict__ A2) {
    int idx = blockIdx.x * blockDim.x + threadIdx.x;   // over (DIMK/2)*LRTOT
    if (idx >= (DIMK / 2) * LRTOT) return;
    int d2 = idx / LRTOT;
    int lr = idx % LRTOT;
    int l  = lr >> 3;
    int r  = lr & 7;
    const float* A = (l == 0) ? A0 : (l == 1) ? A1 : A2;
    g_Apk2[idx] = make_float2(A[(2 * d2) * RR + r], A[(2 * d2 + 1) * RR + r]);
}

// ============================================================
// k1: XA = x @ Acat, split-K x4, cp.async double-buffered.
// Block: 128 threads, 256 rows. Thread tile: 2 rows x 24 lr.
//   thread t -> rows t and t+128, ALL 24 lr (48 f32x2 accs).
// x smem read duplication = 1 (key fix vs R4/R5).
// A reads are warp-uniform 16B broadcasts (all lanes same dp).
// f32x2 accumulator halves = even-d / odd-d partial sums.
// ============================================================
__global__ __launch_bounds__(128, 3) void xa_kernel(const float* __restrict__ x) {
    __shared__ float4 xs[2][DKC / 4][BROWS];     // [buf][d4][row] 2*4*256*16 = 32KB
    __shared__ float2 as2[2][DKC / 2][LRTOT];    // [buf][dp][lr]  2*8*24*8   = 3KB

    int tid = threadIdx.x;                 // 0..127 == row-thread index
    int rowBase = blockIdx.x * BROWS;
    int dBase   = blockIdx.y * (DIMK / KS);
    const int NC = (DIMK / KS) / DKC;      // 64 chunks

    // A staging coords (threads < 96): one 16B = 2 lr of one dp
    int a_dp = tid / 12;                   // 0..7
    int a_q  = tid % 12;                   // lr-pair index

    ull acc[2][LRTOT];                     // [row-half][lr], 48 ull
#pragma unroll
    for (int i = 0; i < 2; i++)
#pragma unroll
        for (int j = 0; j < LRTOT; j++) acc[i][j] = 0ull;

    // ---- staging helper (macro-ish lambda) ----
    auto stage = [&](int buf, int c) {
        int dc = dBase + c * DKC;
        // x: 256 rows x 16 d = 1024 float4, 8 per thread
#pragma unroll
        for (int it = 0; it < 8; it++) {
            int e   = it * 128 + tid;
            int row = e >> 2;
            int d4  = e & 3;
            cp_async16(&xs[buf][d4][row],
                       x + (size_t)(rowBase + row) * DIMK + dc + 4 * d4);
        }
        // A: 8 dp x 24 lr = 96 float2-pairs (16B each)
        if (tid < 96) {
            cp_async16(&as2[buf][a_dp][2 * a_q],
                       g_Apk2 + (size_t)(dc / 2 + a_dp) * LRTOT + 2 * a_q);
        }
        cp_commit();
    };

    stage(0, 0);
    stage(1, 1);

    for (int c = 0; c < NC; c++) {
        int b = c & 1;
        if (c == NC - 1) cp_wait0(); else cp_wait1();   // chunk c landed
        __syncthreads();

        // ---- compute chunk c: 4 d4 groups, 2 d-pairs each ----
#pragma unroll
        for (int d4 = 0; d4 < DKC / 4; d4++) {
            float4 xq0 = xs[b][d4][tid];          // row t    (conflict-free LDS.128)
            float4 xq1 = xs[b][d4][tid + 128];    // row t+128
            ull xp0[2], xp1[2];
            xp0[0] = reinterpret_cast<const ull*>(&xq0)[0];   // (d0,d1) even/odd pair
            xp0[1] = reinterpret_cast<const ull*>(&xq0)[1];   // (d2,d3)
            xp1[0] = reinterpret_cast<const ull*>(&xq1)[0];
            xp1[1] = reinterpret_cast<const ull*>(&xq1)[1];

#pragma unroll
            for (int half = 0; half < 2; half++) {
                int dp = 2 * d4 + half;
                ull x0 = xp0[half];
                ull x1 = xp1[half];
#pragma unroll
                for (int q = 0; q < 12; q++) {    // 12 x 16B broadcast loads
                    ulonglong2 ap = *reinterpret_cast<const ulonglong2*>(
                        &as2[b][dp][2 * q]);
                    ffma2(acc[0][2 * q],     x0, ap.x);
                    ffma2(acc[0][2 * q + 1], x0, ap.y);
                    ffma2(acc[1][2 * q],     x1, ap.x);
                    ffma2(acc[1][2 * q + 1], x1, ap.y);
                }
            }
        }
        __syncthreads();                   // everyone done reading buf b
        if (c + 2 < NC) stage(b, c + 2);   // refill freed buffer
    }

    // ---- writeout: sum even/odd halves, 6 float4 stores per thread ----
#pragma unroll
    for (int i = 0; i < 2; i++) {
        int row = rowBase + tid + 128 * i;
        float v[LRTOT];
#pragma unroll
        for (int j = 0; j < LRTOT; j++) {
            float2 p = *reinterpret_cast<float2*>(&acc[i][j]);
            v[j] = p.x + p.y;
        }
        float* dst = g_xap + (size_t)blockIdx.y * NXA + (size_t)row * LRTOT;
#pragma unroll
        for (int k = 0; k < LRTOT / 4; k++)
            *reinterpret_cast<float4*>(dst + 4 * k) =
                *reinterpret_cast<float4*>(&v[4 * k]);
    }
}

// ============================================================
// k2: out = XA @ B (per lora), f32x2; folds the split-K reduce.
// Grid: (4 col tiles, 512 row tiles, 3 loras). Block: 256 thr.
// Each block: 32 rows x 1024 cols of one lora.
// ============================================================
#define R2ROWS 32

__global__ __launch_bounds__(256, 4) void out_kernel(const float* __restrict__ B0,
                                                     const float* __restrict__ B1,
                                                     const float* __restrict__ B2,
                                                     float* __restrict__ out) {
    int l = blockIdx.z;
    const float* B = (l == 0) ? B0 : (l == 1) ? B1 : B2;
    int rowBase = blockIdx.y * R2ROWS;
    int o = blockIdx.x * 1024 + threadIdx.x * 4;   // column within this lora

    __shared__ float2 xa_s[R2ROWS][RR];            // duplicated (s,s)
    {
        int i = threadIdx.x >> 3;
        int r = threadIdx.x & 7;
        size_t base = (size_t)(rowBase + i) * LRTOT + l * RR + r;
        float s = g_xap[base] + g_xap[NXA + base] +
                  g_xap[2 * (size_t)NXA + base] + g_xap[3 * (size_t)NXA + base];
        xa_s[i][r] = make_float2(s, s);
    }
    __syncthreads();

    // B columns o..o+3 for all 8 r, as f32x2 pairs
    ull blo[RR], bhi[RR];
#pragma unroll
    for (int r = 0; r < RR; r++) {
        float4 b = *reinterpret_cast<const float4*>(B + r * LORA_OUT + o);
        ulonglong2 u = *reinterpret_cast<ulonglong2*>(&b);
        blo[r] = u.x;
        bhi[r] = u.y;
    }

#pragma unroll 4
    for (int i = 0; i < R2ROWS; i++) {
        ull s[RR];
#pragma unroll
        for (int r = 0; r < RR; r++)
            s[r] = *reinterpret_cast<const ull*>(&xa_s[i][r]);   // broadcast

        ull a0 = 0ull, a1 = 0ull;
#pragma unroll
        for (int r = 0; r < RR; r++) {
            ffma2(a0, s[r], blo[r]);
            ffma2(a1, s[r], bhi[r]);
        }
        float4 res;
        *reinterpret_cast<ull*>(&res.x) = a0;
        *reinterpret_cast<ull*>(&res.z) = a1;

        size_t oidx = (size_t)(rowBase + i) * OUT_DIM + (size_t)l * LORA_OUT + o;
        __stcs(reinterpret_cast<float4*>(out + oidx), res);
    }
}

// ============================================================
// launch
// ============================================================
extern "C" void kernel_launch(void* const* d_in, const int* in_sizes, int n_in,
                              void* d_out, int out_size) {
    const float* x  = (const float*)d_in[0];
    const float* A0 = (const float*)d_in[1];
    const float* B0 = (const float*)d_in[2];
    const float* A1 = (const float*)d_in[3];
    const float* B1 = (const float*)d_in[4];
    const float* A2 = (const float*)d_in[5];
    const float* B2 = (const float*)d_in[6];
    float* out = (float*)d_out;

    pack_A_kernel<<<((DIMK / 2) * LRTOT + 255) / 256, 256>>>(A0, A1, A2);

    dim3 grid1(ROWS_TOTAL / BROWS, KS);            // 64 x 4 = 256 blocks
    xa_kernel<<<grid1, 128>>>(x);

    dim3 grid2(LORA_OUT / 1024, ROWS_TOTAL / R2ROWS, NL);  // 4 x 512 x 3
    out_kernel<<<grid2, 256>>>(B0, B1, B2, out);
}

// round 12
// speedup vs baseline: 1.0770x; 1.0770x over previous
#include <cuda_runtime.h>
#include <cstdint>

// Problem constants
#define ROWS_TOTAL 16384      // 4 * 4096 (batch * seq)
#define DIMK 4096             // inner dim
#define RR 8                  // LoRA rank
#define NL 3                  // number of LoRAs
#define LRTOT 24              // NL * RR
#define OUT_DIM 12288         // NL * 4096
#define LORA_OUT 4096

#define NXA (ROWS_TOTAL * LRTOT)   // 393216
#define KS  4                      // split-K slices
#define DKC 16                     // d per chunk
#define BROWS 256                  // rows per xa block

typedef unsigned long long ull;

// -------- scratch (no allocations allowed) --------
__device__ float2 g_Apk2[(DIMK / 2) * LRTOT];  // A packed as d-pairs: [d2][lr]
__device__ float  g_xap[KS * NXA];             // XA partials per k-slice

__device__ __forceinline__ void ffma2(ull& acc, ull a, ull b) {
    asm("fma.rn.f32x2 %0, %1, %2, %0;" : "+l"(acc) : "l"(a), "l"(b));
}

__device__ __forceinline__ void cp_async16(void* smem_dst, const void* gptr) {
    unsigned s = (unsigned)__cvta_generic_to_shared(smem_dst);
    asm volatile("cp.async.cg.shared.global [%0], [%1], 16;\n" :: "r"(s), "l"(gptr));
}
__device__ __forceinline__ void cp_commit() {
    asm volatile("cp.async.commit_group;\n" ::: "memory");
}
__device__ __forceinline__ void cp_wait1() {
    asm volatile("cp.async.wait_group 1;\n" ::: "memory");
}
__device__ __forceinline__ void cp_wait0() {
    asm volatile("cp.async.wait_group 0;\n" ::: "memory");
}

// ============================================================
// k0: pack A0/A1/A2 ([dim][r] row-major) -> g_Apk2 [d2][lr] float2
// ============================================================
__global__ void pack_A_kernel(const float* __restrict__ A0,
                              const float* __restrict__ A1,
                              const float* __restrict__ A2) {
    int idx = blockIdx.x * blockDim.x + threadIdx.x;   // over (DIMK/2)*LRTOT
    if (idx >= (DIMK / 2) * LRTOT) return;
    int d2 = idx / LRTOT;
    int lr = idx % LRTOT;
    int l  = lr >> 3;
    int r  = lr & 7;
    const float* A = (l == 0) ? A0 : (l == 1) ? A1 : A2;
    g_Apk2[idx] = make_float2(A[(2 * d2) * RR + r], A[(2 * d2 + 1) * RR + r]);
}

// ============================================================
// k1: XA = x @ Acat, split-K x4, cp.async double-buffered.
// Block: 256 threads, 256 rows. Thread tile: 4 rows x 6 lr.
//   rg = tid & 63 -> rows rg + 64*i (i=0..3)
//   lg = tid >> 6 -> lrs  lg*6 + j  (j=0..5)
// acc = 24 ull = 48 regs (no spill; bounds(256,2) cap=128).
// LDS per d4 group: 4 x-LDS.128 (conflict-free) + 6 A-LDS.128
// (warp-uniform broadcast) for 48 FFMA2 -> ratio 0.21.
// f32x2 accumulator halves = even-d / odd-d partial sums.
// ============================================================
__global__ __launch_bounds__(256, 2) void xa_kernel(const float* __restrict__ x) {
    __shared__ float4 xs[2][DKC / 4][BROWS];     // [buf][d4][row] 2*4*256*16 = 32KB
    __shared__ float2 as2[2][DKC / 2][LRTOT];    // [buf][dp][lr]  2*8*24*8   = 3KB

    int tid = threadIdx.x;
    int rg  = tid & 63;
    int lg  = tid >> 6;                    // 0..3
    int rowBase = blockIdx.x * BROWS;
    int dBase   = blockIdx.y * (DIMK / KS);
    const int NC = (DIMK / KS) / DKC;      // 64 chunks

    // A staging coords (threads < 96): one 16B = 2 lr of one dp
    int a_dp = tid / 12;                   // 0..7
    int a_q  = tid % 12;                   // lr-pair index

    ull acc[4][6];                         // [row][lr], 24 ull = 48 regs
#pragma unroll
    for (int i = 0; i < 4; i++)
#pragma unroll
        for (int j = 0; j < 6; j++) acc[i][j] = 0ull;

    auto stage = [&](int buf, int c) {
        int dc = dBase + c * DKC;
        // x: 256 rows x 16 d = 1024 float4, 4 per thread
#pragma unroll
        for (int it = 0; it < 4; it++) {
            int e   = it * 256 + tid;
            int row = e >> 2;
            int d4  = e & 3;
            cp_async16(&xs[buf][d4][row],
                       x + (size_t)(rowBase + row) * DIMK + dc + 4 * d4);
        }
        // A: 8 dp x 24 lr = 96 x 16B
        if (tid < 96) {
            cp_async16(&as2[buf][a_dp][2 * a_q],
                       g_Apk2 + (size_t)(dc / 2 + a_dp) * LRTOT + 2 * a_q);
        }
        cp_commit();
    };

    stage(0, 0);
    stage(1, 1);

    for (int c = 0; c < NC; c++) {
        int b = c & 1;
        if (c == NC - 1) cp_wait0(); else cp_wait1();   // chunk c landed
        __syncthreads();

        // ---- compute chunk c: 4 d4 groups, 2 d-pairs each ----
#pragma unroll
        for (int d4 = 0; d4 < DKC / 4; d4++) {
            // x: 4 rows, full float4 (both d-pairs), conflict-free LDS.128
            float4 xq[4];
#pragma unroll
            for (int i = 0; i < 4; i++)
                xq[i] = xs[b][d4][rg + 64 * i];

#pragma unroll
            for (int half = 0; half < 2; half++) {
                int dp = 2 * d4 + half;
                // A: 6 lr = 3 x 16B warp-uniform broadcast loads
                ull ap[6];
#pragma unroll
                for (int q = 0; q < 3; q++) {
                    ulonglong2 t = *reinterpret_cast<const ulonglong2*>(
                        &as2[b][dp][lg * 6 + 2 * q]);
                    ap[2 * q]     = t.x;
                    ap[2 * q + 1] = t.y;
                }
                ull xp[4];
#pragma unroll
                for (int i = 0; i < 4; i++)
                    xp[i] = reinterpret_cast<const ull*>(&xq[i])[half];
#pragma unroll
                for (int i = 0; i < 4; i++)
#pragma unroll
                    for (int j = 0; j < 6; j++)
                        ffma2(acc[i][j], xp[i], ap[j]);
            }
        }
        __syncthreads();                   // everyone done reading buf b
        if (c + 2 < NC) stage(b, c + 2);   // refill freed buffer
    }

    // ---- writeout: sum even/odd halves, 3 float2 stores per row ----
#pragma unroll
    for (int i = 0; i < 4; i++) {
        int row = rowBase + rg + 64 * i;
        float v[6];
#pragma unroll
        for (int j = 0; j < 6; j++) {
            float2 p = *reinterpret_cast<float2*>(&acc[i][j]);
            v[j] = p.x + p.y;
        }
        float* dst = g_xap + (size_t)blockIdx.y * NXA
                   + (size_t)row * LRTOT + lg * 6;
#pragma unroll
        for (int k = 0; k < 3; k++)
            *reinterpret_cast<float2*>(dst + 2 * k) =
                *reinterpret_cast<float2*>(&v[2 * k]);
    }
}

// ============================================================
// k2: out = XA @ B (per lora), f32x2; folds the split-K reduce.
// Grid: (4 col tiles, 512 row tiles, 3 loras). Block: 256 thr.
// Each block: 32 rows x 1024 cols of one lora.
// ============================================================
#define R2ROWS 32

__global__ __launch_bounds__(256, 4) void out_kernel(const float* __restrict__ B0,
                                                     const float* __restrict__ B1,
                                                     const float* __restrict__ B2,
                                                     float* __restrict__ out) {
    int l = blockIdx.z;
    const float* B = (l == 0) ? B0 : (l == 1) ? B1 : B2;
    int rowBase = blockIdx.y * R2ROWS;
    int o = blockIdx.x * 1024 + threadIdx.x * 4;   // column within this lora

    __shared__ float2 xa_s[R2ROWS][RR];            // duplicated (s,s)
    {
        int i = threadIdx.x >> 3;
        int r = threadIdx.x & 7;
        size_t base = (size_t)(rowBase + i) * LRTOT + l * RR + r;
        float s = g_xap[base] + g_xap[NXA + base] +
                  g_xap[2 * (size_t)NXA + base] + g_xap[3 * (size_t)NXA + base];
        xa_s[i][r] = make_float2(s, s);
    }
    __syncthreads();

    // B columns o..o+3 for all 8 r, as f32x2 pairs
    ull blo[RR], bhi[RR];
#pragma unroll
    for (int r = 0; r < RR; r++) {
        float4 b = *reinterpret_cast<const float4*>(B + r * LORA_OUT + o);
        ulonglong2 u = *reinterpret_cast<ulonglong2*>(&b);
        blo[r] = u.x;
        bhi[r] = u.y;
    }

#pragma unroll 4
    for (int i = 0; i < R2ROWS; i++) {
        ull s[RR];
#pragma unroll
        for (int r = 0; r < RR; r++)
            s[r] = *reinterpret_cast<const ull*>(&xa_s[i][r]);   // broadcast

        ull a0 = 0ull, a1 = 0ull;
#pragma unroll
        for (int r = 0; r < RR; r++) {
            ffma2(a0, s[r], blo[r]);
            ffma2(a1, s[r], bhi[r]);
        }
        float4 res;
        *reinterpret_cast<ull*>(&res.x) = a0;
        *reinterpret_cast<ull*>(&res.z) = a1;

        size_t oidx = (size_t)(rowBase + i) * OUT_DIM + (size_t)l * LORA_OUT + o;
        __stcs(reinterpret_cast<float4*>(out + oidx), res);
    }
}

// ============================================================
// launch
// ============================================================
extern "C" void kernel_launch(void* const* d_in, const int* in_sizes, int n_in,
                              void* d_out, int out_size) {
    const float* x  = (const float*)d_in[0];
    const float* A0 = (const float*)d_in[1];
    const float* B0 = (const float*)d_in[2];
    const float* A1 = (const float*)d_in[3];
    const float* B1 = (const float*)d_in[4];
    const float* A2 = (const float*)d_in[5];
    const float* B2 = (const float*)d_in[6];
    float* out = (float*)d_out;

    pack_A_kernel<<<((DIMK / 2) * LRTOT + 255) / 256, 256>>>(A0, A1, A2);

    dim3 grid1(ROWS_TOTAL / BROWS, KS);            // 64 x 4 = 256 blocks
    xa_kernel<<<grid1, 256>>>(x);

    dim3 grid2(LORA_OUT / 1024, ROWS_TOTAL / R2ROWS, NL);  // 4 x 512 x 3
    out_kernel<<<grid2, 256>>>(B0, B1, B2, out);
}

// round 17
// speedup vs baseline: 1.5635x; 1.4517x over previous
#include <cuda_runtime.h>
#include <cuda.h>
#include <cstdint>
#include <dlfcn.h>

// Problem constants
#define ROWS_TOTAL 16384      // 4 * 4096 (batch * seq)
#define DIMK 4096             // inner dim
#define RR 8                  // LoRA rank
#define NL 3                  // number of LoRAs
#define LRTOT 24              // NL * RR
#define NPAD 32               // padded N for MMA
#define OUT_DIM 12288         // NL * 4096
#define LORA_OUT 4096

#define MTILE 128             // rows per CTA (xa)
#define KC 32                 // k elems per chunk (128B rows)
#define NCH (DIMK / KC)       // 128 chunks
#define NSTAGE 4

#define XTILE_B (MTILE * KC * 4)   // 16384 B
#define BTILE_B (NPAD * KC * 4)    // 4096 B

typedef unsigned long long ull;

// tcgen05 is an arch-accelerated feature: only present in the sm_103a pass.
#if defined(__CUDA_ARCH__) && defined(__CUDA_ARCH_FEAT_SM103_ALL)
#define HAS_TCG 1
#else
#define HAS_TCG 0
#endif

// -------- scratch (no allocations allowed) --------
__device__ __align__(1024) float g_Apk32[NPAD * DIMK];  // A padded [lr(32)][d]
__device__ float g_xa[ROWS_TOTAL * LRTOT];              // XA [row][24]

// idesc: dtype F32 (1<<4), atype TF32 (2<<7), btype TF32 (2<<10),
// N>>3 (<<17), M>>4 (<<24). bf16 variant reproduces test_mma's 0x8080490.
#define IDESC_TF32 ((1u << 4) | (2u << 7) | (2u << 10) | ((NPAD / 8) << 17) | ((MTILE / 16) << 24))

// SW128 K-major smem descriptor base: layout=2, version=1, SBO=64, LBO=1
#define DESC_BASE ((2ull << 61) | (1ull << 46) | (64ull << 32) | (1ull << 16))
__device__ __forceinline__ ull make_desc(unsigned addr) {
    return DESC_BASE | ((ull)(addr >> 4) & 0x3FFF);
}
__device__ __forceinline__ unsigned smem_u32(const void* p) {
    return (unsigned)__cvta_generic_to_shared(p);
}

__device__ __forceinline__ void mbar_init(unsigned a, unsigned cnt) {
    asm volatile("mbarrier.init.shared.b64 [%0], %1;" :: "r"(a), "r"(cnt) : "memory");
}
__device__ __forceinline__ void mbar_expect(unsigned a, unsigned bytes) {
    asm volatile("mbarrier.arrive.expect_tx.shared.b64 _, [%0], %1;" :: "r"(a), "r"(bytes) : "memory");
}
__device__ __forceinline__ void mbar_waitp(unsigned a, unsigned ph) {
    unsigned done = 0;
    while (!done) {
        asm volatile(
            "{\n\t.reg .pred P;\n\t"
            "mbarrier.try_wait.parity.shared.b64 P, [%1], %2, 0x989680;\n\t"
            "selp.b32 %0, 1, 0, P;\n\t}"
            : "=r"(done) : "r"(a), "r"(ph) : "memory");
    }
}
__device__ __forceinline__ void tma2d(unsigned dst, const CUtensorMap* tm,
                                      int cx, int cy, unsigned mbar) {
    asm volatile(
        "cp.async.bulk.tensor.2d.shared::cta.global.tile.mbarrier::complete_tx::bytes "
        "[%0], [%1, {%2, %3}], [%4];"
        :: "r"(dst), "l"(tm), "r"(cx), "r"(cy), "r"(mbar) : "memory");
}

#if HAS_TCG
__device__ __forceinline__ void mma_tf32(unsigned d, ull ad, ull bd, unsigned en) {
    asm volatile(
        "{\n\t.reg .pred p;\n\tsetp.ne.u32 p, %4, 0;\n\t"
        "tcgen05.mma.cta_group::1.kind::tf32 [%0], %1, %2, %3, {%5, %5, %5, %5}, p;\n\t}"
        :: "r"(d), "l"(ad), "l"(bd), "r"(IDESC_TF32), "r"(en), "r"(0u) : "memory");
}
__device__ __forceinline__ void mma_commit(unsigned mbar) {
    asm volatile(
        "tcgen05.commit.cta_group::1.mbarrier::arrive::one.shared::cluster.b64 [%0];"
        :: "r"(mbar) : "memory");
}
#endif

// ============================================================
// k0: pack A0/A1/A2 ([dim][r]) -> g_Apk32 [lr(32)][d], rows 24..31 zero
// ============================================================
__global__ void pack_A_kernel(const float* __restrict__ A0,
                              const float* __restrict__ A1,
                              const float* __restrict__ A2) {
    int idx = blockIdx.x * blockDim.x + threadIdx.x;   // over NPAD*DIMK
    if (idx >= NPAD * DIMK) return;
    int lr = idx / DIMK;
    int d  = idx % DIMK;
    float v = 0.0f;
    if (lr < LRTOT) {
        int l = lr >> 3;
        int r = lr & 7;
        const float* A = (l == 0) ? A0 : (l == 1) ? A1 : A2;
        v = A[d * RR + r];
    }
    g_Apk32[idx] = v;
}

// ============================================================
// k1: XA. sm_103a pass: tcgen05 tf32 (TMA pipeline, TMEM acc).
// Non-accelerated pass: scalar fallback, SAME launch shape
// (grid 128, block 128): thread = 1 row, 24 accumulators.
// ============================================================
__global__ __launch_bounds__(128, 1) void xa_kernel(
    const __grid_constant__ CUtensorMap tmx,
    const __grid_constant__ CUtensorMap tmb,
    const float* __restrict__ x) {
#if HAS_TCG
    extern __shared__ char dyn_smem[];
    __shared__ __align__(8) ull mbars[2 * NSTAGE + 1];  // full[4], empty[4], final
    __shared__ unsigned tmem_slot[1];

    int tid = threadIdx.x;
    int wid = tid >> 5;
    int lid = tid & 31;
    int rowBase = blockIdx.x * MTILE;

    unsigned smem_base = (smem_u32(dyn_smem) + 1023u) & ~1023u;
    unsigned xs = smem_base;                       // 4 x-tiles of 16KB
    unsigned bs = smem_base + NSTAGE * XTILE_B;    // 4 b-tiles of 4KB
    unsigned mb = smem_u32(mbars);
    unsigned full0  = mb;
    unsigned empty0 = mb + 8 * NSTAGE;
    unsigned finalb = mb + 16 * NSTAGE;

    if (tid == 0) {
        for (int s = 0; s < NSTAGE; s++) {
            mbar_init(full0 + 8 * s, 1);
            mbar_init(empty0 + 8 * s, 1);
        }
        mbar_init(finalb, 1);
    }
    if (wid == 0) {
        asm volatile(
            "tcgen05.alloc.cta_group::1.sync.aligned.shared::cta.b32 [%0], %1;"
            :: "r"(smem_u32(tmem_slot)), "r"(512u) : "memory");
    }
    __syncthreads();
    unsigned tmem_base = tmem_slot[0];

    if (tid == 0) {
        for (int c = 0; c < NSTAGE; c++) {        // prefill stages
            unsigned f = full0 + 8 * c;
            mbar_expect(f, XTILE_B + BTILE_B);
            tma2d(xs + c * XTILE_B, &tmx, c * KC, rowBase, f);
            tma2d(bs + c * BTILE_B, &tmb, c * KC, 0, f);
        }
        for (int c = 0; c < NCH; c++) {
            int s = c & (NSTAGE - 1);
            unsigned ph = (c >> 2) & 1;
            mbar_waitp(full0 + 8 * s, ph);
            ull ad = make_desc(xs + s * XTILE_B);
            ull bd = make_desc(bs + s * BTILE_B);
            mma_tf32(tmem_base, ad + 0, bd + 0, c > 0);
            mma_tf32(tmem_base, ad + 2, bd + 2, 1);
            mma_tf32(tmem_base, ad + 4, bd + 4, 1);
            mma_tf32(tmem_base, ad + 6, bd + 6, 1);
            if (c == NCH - 1) {
                mma_commit(finalb);
            } else {
                mma_commit(empty0 + 8 * s);
                if (c + NSTAGE < NCH) {
                    mbar_waitp(empty0 + 8 * s, ph);   // stage's MMAs done
                    unsigned f = full0 + 8 * s;
                    mbar_expect(f, XTILE_B + BTILE_B);
                    tma2d(xs + s * XTILE_B, &tmx, (c + NSTAGE) * KC, rowBase, f);
                    tma2d(bs + s * BTILE_B, &tmb, (c + NSTAGE) * KC, 0, f);
                }
            }
        }
    }

    mbar_waitp(finalb, 0);
    asm volatile("tcgen05.fence::after_thread_sync;" ::: "memory");

    // epilogue: warp w reads D rows w*32..w*32+31, cols 0..31
    unsigned d_regs[32];
    asm volatile(
        "tcgen05.ld.sync.aligned.32x32b.x32.b32 "
        "{%0, %1, %2, %3, %4, %5, %6, %7, "
        " %8, %9, %10, %11, %12, %13, %14, %15, "
        " %16, %17, %18, %19, %20, %21, %22, %23, "
        " %24, %25, %26, %27, %28, %29, %30, %31}, [%32];"
        : "=r"(d_regs[0]),  "=r"(d_regs[1]),  "=r"(d_regs[2]),  "=r"(d_regs[3]),
          "=r"(d_regs[4]),  "=r"(d_regs[5]),  "=r"(d_regs[6]),  "=r"(d_regs[7]),
          "=r"(d_regs[8]),  "=r"(d_regs[9]),  "=r"(d_regs[10]), "=r"(d_regs[11]),
          "=r"(d_regs[12]), "=r"(d_regs[13]), "=r"(d_regs[14]), "=r"(d_regs[15]),
          "=r"(d_regs[16]), "=r"(d_regs[17]), "=r"(d_regs[18]), "=r"(d_regs[19]),
          "=r"(d_regs[20]), "=r"(d_regs[21]), "=r"(d_regs[22]), "=r"(d_regs[23]),
          "=r"(d_regs[24]), "=r"(d_regs[25]), "=r"(d_regs[26]), "=r"(d_regs[27]),
          "=r"(d_regs[28]), "=r"(d_regs[29]), "=r"(d_regs[30]), "=r"(d_regs[31])
        : "r"(tmem_base));
    asm volatile("tcgen05.wait::ld.sync.aligned;" ::: "memory");

    int row = rowBase + wid * 32 + lid;
    float* dst = g_xa + (size_t)row * LRTOT;
#pragma unroll
    for (int j = 0; j < LRTOT; j++)
        dst[j] = __uint_as_float(d_regs[j]);

    __syncthreads();
    if (wid == 0) {
        asm volatile("tcgen05.relinquish_alloc_permit.cta_group::1.sync.aligned;");
        asm volatile("tcgen05.dealloc.cta_group::1.sync.aligned.b32 %0, %1;"
                     :: "r"(tmem_base), "r"(512u));
    }
#else
    // ---------- scalar fallback (non-sm_103a pass) ----------
    __shared__ float fxs[KC][MTILE + 1];     // [d][row]
    __shared__ __align__(16) float fas[KC][LRTOT];  // [d][lr] (row = 96B, 16B-aligned)

    int tid = threadIdx.x;                   // thread = row
    int rowBase = blockIdx.x * MTILE;

    float acc[LRTOT];
#pragma unroll
    for (int j = 0; j < LRTOT; j++) acc[j] = 0.0f;

    for (int dc = 0; dc < DIMK; dc += KC) {
        // stage x: 128 rows x 32 d = 1024 float4, 8 per thread
#pragma unroll
        for (int it = 0; it < 8; it++) {
            int e   = it * 128 + tid;
            int row = e >> 3;
            int d4  = e & 7;
            float4 v = reinterpret_cast<const float4*>(
                x + (size_t)(rowBase + row) * DIMK + dc)[d4];
            fxs[4 * d4 + 0][row] = v.x;
            fxs[4 * d4 + 1][row] = v.y;
            fxs[4 * d4 + 2][row] = v.z;
            fxs[4 * d4 + 3][row] = v.w;
        }
        // stage A: 32 d x 24 lr = 768 floats, 6 per thread
#pragma unroll
        for (int it = 0; it < 6; it++) {
            int e  = it * 128 + tid;
            int lr = e >> 5;
            int d  = e & 31;
            fas[d][lr] = g_Apk32[(size_t)lr * DIMK + dc + d];
        }
        __syncthreads();

#pragma unroll 8
        for (int d = 0; d < KC; d++) {
            float xv = fxs[d][tid];
#pragma unroll
            for (int q = 0; q < 6; q++) {
                float4 ap = *reinterpret_cast<const float4*>(&fas[d][4 * q]);
                acc[4 * q + 0] += xv * ap.x;
                acc[4 * q + 1] += xv * ap.y;
                acc[4 * q + 2] += xv * ap.z;
                acc[4 * q + 3] += xv * ap.w;
            }
        }
        __syncthreads();
    }

    float* dst = g_xa + (size_t)(rowBase + tid) * LRTOT;
#pragma unroll
    for (int q = 0; q < 6; q++)
        *reinterpret_cast<float4*>(dst + 4 * q) =
            make_float4(acc[4 * q], acc[4 * q + 1], acc[4 * q + 2], acc[4 * q + 3]);
#endif
}

// ============================================================
// k2: out = XA @ B (per lora), f32x2. 32 rows x 1024 cols per block.
// ============================================================
#define R2ROWS 32

__device__ __forceinline__ void ffma2(ull& acc, ull a, ull b) {
    asm("fma.rn.f32x2 %0, %1, %2, %0;" : "+l"(acc) : "l"(a), "l"(b));
}

__global__ __launch_bounds__(256, 4) void out_kernel(const float* __restrict__ B0,
                                                     const float* __restrict__ B1,
                                                     const float* __restrict__ B2,
                                                     float* __restrict__ out) {
    int l = blockIdx.z;
    const float* B = (l == 0) ? B0 : (l == 1) ? B1 : B2;
    int rowBase = blockIdx.y * R2ROWS;
    int o = blockIdx.x * 1024 + threadIdx.x * 4;   // column within this lora

    __shared__ float2 xa_s[R2ROWS][RR];            // duplicated (s,s)
    {
        int i = threadIdx.x >> 3;
        int r = threadIdx.x & 7;
        float s = g_xa[(size_t)(rowBase + i) * LRTOT + l * RR + r];
        xa_s[i][r] = make_float2(s, s);
    }
    __syncthreads();

    ull blo[RR], bhi[RR];
#pragma unroll
    for (int r = 0; r < RR; r++) {
        float4 b = *reinterpret_cast<const float4*>(B + r * LORA_OUT + o);
        ulonglong2 u = *reinterpret_cast<ulonglong2*>(&b);
        blo[r] = u.x;
        bhi[r] = u.y;
    }

#pragma unroll 4
    for (int i = 0; i < R2ROWS; i++) {
        ull s[RR];
#pragma unroll
        for (int r = 0; r < RR; r++)
            s[r] = *reinterpret_cast<const ull*>(&xa_s[i][r]);

        ull a0 = 0ull, a1 = 0ull;
#pragma unroll
        for (int r = 0; r < RR; r++) {
            ffma2(a0, s[r], blo[r]);
            ffma2(a1, s[r], bhi[r]);
        }
        float4 res;
        *reinterpret_cast<ull*>(&res.x) = a0;
        *reinterpret_cast<ull*>(&res.z) = a1;

        size_t oidx = (size_t)(rowBase + i) * OUT_DIM + (size_t)l * LORA_OUT + o;
        __stcs(reinterpret_cast<float4*>(out + oidx), res);
    }
}

// ============================================================
// launch (host)
// ============================================================
typedef CUresult (*EncodeFn)(CUtensorMap*, CUtensorMapDataType, cuuint32_t, void*,
                             const cuuint64_t*, const cuuint64_t*, const cuuint32_t*,
                             const cuuint32_t*, CUtensorMapInterleave, CUtensorMapSwizzle,
                             CUtensorMapL2promotion, CUtensorMapFloatOOBfill);

extern "C" void kernel_launch(void* const* d_in, const int* in_sizes, int n_in,
                              void* d_out, int out_size) {
    const float* x  = (const float*)d_in[0];
    const float* A0 = (const float*)d_in[1];
    const float* B0 = (const float*)d_in[2];
    const float* A1 = (const float*)d_in[3];
    const float* B1 = (const float*)d_in[4];
    const float* A2 = (const float*)d_in[5];
    const float* B2 = (const float*)d_in[6];
    float* out = (float*)d_out;

    // resolve driver encode fn (host-side, no -lcuda link needed)
    void* h = dlopen("libcuda.so.1", RTLD_LAZY | RTLD_GLOBAL);
    if (!h) h = dlopen("libcuda.so", RTLD_LAZY | RTLD_GLOBAL);
    EncodeFn enc = h ? (EncodeFn)dlsym(h, "cuTensorMapEncodeTiled") : nullptr;

    void* apk_ptr = nullptr;
    cudaGetSymbolAddress(&apk_ptr, g_Apk32);

    CUtensorMap tmx = {}, tmb = {};
    if (enc) {
        {
            cuuint64_t dims[2]    = {DIMK, ROWS_TOTAL};
            cuuint64_t strides[1] = {(cuuint64_t)DIMK * 4};
            cuuint32_t box[2]     = {KC, MTILE};
            cuuint32_t es[2]      = {1, 1};
            enc(&tmx, CU_TENSOR_MAP_DATA_TYPE_FLOAT32, 2, (void*)x,
                dims, strides, box, es,
                CU_TENSOR_MAP_INTERLEAVE_NONE, CU_TENSOR_MAP_SWIZZLE_128B,
                CU_TENSOR_MAP_L2_PROMOTION_L2_128B, CU_TENSOR_MAP_FLOAT_OOB_FILL_NONE);
        }
        {
            cuuint64_t dims[2]    = {DIMK, NPAD};
            cuuint64_t strides[1] = {(cuuint64_t)DIMK * 4};
            cuuint32_t box[2]     = {KC, NPAD};
            cuuint32_t es[2]      = {1, 1};
            enc(&tmb, CU_TENSOR_MAP_DATA_TYPE_FLOAT32, 2, apk_ptr,
                dims, strides, box, es,
                CU_TENSOR_MAP_INTERLEAVE_NONE, CU_TENSOR_MAP_SWIZZLE_128B,
                CU_TENSOR_MAP_L2_PROMOTION_L2_128B, CU_TENSOR_MAP_FLOAT_OOB_FILL_NONE);
        }
    }

    pack_A_kernel<<<(NPAD * DIMK + 255) / 256, 256>>>(A0, A1, A2);

    int dyn = NSTAGE * (XTILE_B + BTILE_B) + 2048;   // 83968 (ignored by fallback)
    cudaFuncSetAttribute(xa_kernel, cudaFuncAttributeMaxDynamicSharedMemorySize, 120000);
    xa_kernel<<<ROWS_TOTAL / MTILE, 128, dyn>>>(tmx, tmb, x);

    dim3 grid2(LORA_OUT / 1024, ROWS_TOTAL / R2ROWS, NL);  // 4 x 512 x 3
    out_kernel<<<grid2, 256>>>(B0, B1, B2, out);
}